// round 1
// baseline (speedup 1.0000x reference)
#include <cuda_runtime.h>
#include <cuda_bf16.h>
#include <math_constants.h>

// Problem constants (fixed by the reference):
//   x:  [N, D] fp32,  cb: [K, D] fp32 (L2-normalized rows)
//   sims = x @ cb^T  [N, K];  labels = argmax_k sims (first occurrence); preds = cb[labels]
#define NN 131072
#define DD 512
#define KK 2048

#define BM 128
#define BN 128
#define BK 16

// ---------------------------------------------------------------------------
// Kernel 1: fp32 SGEMM (NT): C[n,k] = sum_d A[n,d] * B[k,d]
// 128x128 block tile, BK=16, 256 threads, 8x8 per-thread microtile.
// ---------------------------------------------------------------------------
__global__ __launch_bounds__(256, 2)
void sgemm_nt_kernel(const float* __restrict__ A,
                     const float* __restrict__ B,
                     float* __restrict__ C)
{
    __shared__ float As[BK][BM + 4];
    __shared__ float Bs[BK][BN + 4];

    const int tid = threadIdx.x;
    const int bm = blockIdx.y * BM;
    const int bn = blockIdx.x * BN;

    // Global-load mapping: 512 float4 per operand per tile, 2 per thread.
    const int lrow = tid >> 2;          // 0..63  (second load covers +64)
    const int lc4  = (tid & 3) * 4;     // 0,4,8,12 within BK

    const float* Aptr = A + (size_t)(bm + lrow) * DD + lc4;
    const float* Bptr = B + (size_t)(bn + lrow) * DD + lc4;

    // Compute mapping: 16x16 thread grid, each owns rows {rb..rb+3, rb+64..}, cols likewise.
    const int rowBase = (tid >> 4) * 4;   // 0..60
    const int colBase = (tid & 15) * 4;   // 0..60

    float acc[8][8];
#pragma unroll
    for (int i = 0; i < 8; ++i)
#pragma unroll
        for (int j = 0; j < 8; ++j) acc[i][j] = 0.0f;

    // Prefetch tile 0 into registers
    float4 pa0 = *(const float4*)(Aptr);
    float4 pa1 = *(const float4*)(Aptr + (size_t)64 * DD);
    float4 pb0 = *(const float4*)(Bptr);
    float4 pb1 = *(const float4*)(Bptr + (size_t)64 * DD);

    for (int kk = 0; kk < DD; kk += BK) {
        // Store prefetched tile into smem (transposed)
        As[lc4 + 0][lrow] = pa0.x;  As[lc4 + 1][lrow] = pa0.y;
        As[lc4 + 2][lrow] = pa0.z;  As[lc4 + 3][lrow] = pa0.w;
        As[lc4 + 0][lrow + 64] = pa1.x;  As[lc4 + 1][lrow + 64] = pa1.y;
        As[lc4 + 2][lrow + 64] = pa1.z;  As[lc4 + 3][lrow + 64] = pa1.w;
        Bs[lc4 + 0][lrow] = pb0.x;  Bs[lc4 + 1][lrow] = pb0.y;
        Bs[lc4 + 2][lrow] = pb0.z;  Bs[lc4 + 3][lrow] = pb0.w;
        Bs[lc4 + 0][lrow + 64] = pb1.x;  Bs[lc4 + 1][lrow + 64] = pb1.y;
        Bs[lc4 + 2][lrow + 64] = pb1.z;  Bs[lc4 + 3][lrow + 64] = pb1.w;
        __syncthreads();

        // Prefetch next tile (overlaps with compute below)
        if (kk + BK < DD) {
            Aptr += BK; Bptr += BK;
            pa0 = *(const float4*)(Aptr);
            pa1 = *(const float4*)(Aptr + (size_t)64 * DD);
            pb0 = *(const float4*)(Bptr);
            pb1 = *(const float4*)(Bptr + (size_t)64 * DD);
        }

#pragma unroll
        for (int p = 0; p < BK; ++p) {
            float4 ra0 = *(const float4*)(&As[p][rowBase]);
            float4 ra1 = *(const float4*)(&As[p][rowBase + 64]);
            float4 rb0 = *(const float4*)(&Bs[p][colBase]);
            float4 rb1 = *(const float4*)(&Bs[p][colBase + 64]);
            float a[8] = {ra0.x, ra0.y, ra0.z, ra0.w, ra1.x, ra1.y, ra1.z, ra1.w};
            float b[8] = {rb0.x, rb0.y, rb0.z, rb0.w, rb1.x, rb1.y, rb1.z, rb1.w};
#pragma unroll
            for (int i = 0; i < 8; ++i)
#pragma unroll
                for (int j = 0; j < 8; ++j)
                    acc[i][j] = fmaf(a[i], b[j], acc[i][j]);
        }
        __syncthreads();
    }

    // Write back: rows {rowBase+i, rowBase+64+i}, cols {colBase.., colBase+64..}
#pragma unroll
    for (int i = 0; i < 8; ++i) {
        int r = bm + ((i < 4) ? (rowBase + i) : (rowBase + 64 + (i - 4)));
        float4 v0 = make_float4(acc[i][0], acc[i][1], acc[i][2], acc[i][3]);
        float4 v1 = make_float4(acc[i][4], acc[i][5], acc[i][6], acc[i][7]);
        float* crow = C + (size_t)r * KK + bn;
        *(float4*)(crow + colBase)      = v0;
        *(float4*)(crow + colBase + 64) = v1;
    }
}

// ---------------------------------------------------------------------------
// Kernel 2: per-row argmax (first-occurrence tie-break, matching jnp.argmax)
// fused with codebook gather (preds) and label store.
// One block (256 threads) per row.
// ---------------------------------------------------------------------------
__global__ __launch_bounds__(256)
void argmax_gather_kernel(const float* __restrict__ sims,
                          const float* __restrict__ cb,
                          float* __restrict__ preds,
                          void* __restrict__ labels,
                          int labels_are_i64)
{
    const int n = blockIdx.x;
    const int tid = threadIdx.x;
    const float4* row = (const float4*)(sims + (size_t)n * KK);

    float bv = -CUDART_INF_F;
    int   bi = 0;
#pragma unroll
    for (int it = 0; it < 2; ++it) {
        int j = tid + it * 256;          // increasing index order within thread
        float4 v = row[j];
        int base = j * 4;
        if (v.x > bv) { bv = v.x; bi = base; }
        if (v.y > bv) { bv = v.y; bi = base + 1; }
        if (v.z > bv) { bv = v.z; bi = base + 2; }
        if (v.w > bv) { bv = v.w; bi = base + 3; }
    }

    // Warp reduce (max value; on tie, min index)
#pragma unroll
    for (int off = 16; off > 0; off >>= 1) {
        float ov = __shfl_down_sync(0xFFFFFFFFu, bv, off);
        int   oi = __shfl_down_sync(0xFFFFFFFFu, bi, off);
        if (ov > bv || (ov == bv && oi < bi)) { bv = ov; bi = oi; }
    }

    __shared__ float sv[8];
    __shared__ int   si[8];
    __shared__ int   finalIdx;
    const int lane = tid & 31, warp = tid >> 5;
    if (lane == 0) { sv[warp] = bv; si[warp] = bi; }
    __syncthreads();
    if (tid == 0) {
        float fv = sv[0]; int fi = si[0];
#pragma unroll
        for (int w = 1; w < 8; ++w)
            if (sv[w] > fv || (sv[w] == fv && si[w] < fi)) { fv = sv[w]; fi = si[w]; }
        finalIdx = fi;
        if (labels_are_i64) ((long long*)labels)[n] = (long long)fi;
        else                ((float*)labels)[n] = (float)fi;
    }
    __syncthreads();

    const int lbl = finalIdx;
    // Gather preds row: 512 floats = 128 float4 (threads 0..127)
    if (tid < 128) {
        float4 c = ((const float4*)(cb + (size_t)lbl * DD))[tid];
        ((float4*)(preds + (size_t)n * DD))[tid] = c;
    }
}

// ---------------------------------------------------------------------------
// Launch
// ---------------------------------------------------------------------------
extern "C" void kernel_launch(void* const* d_in, const int* in_sizes, int n_in,
                              void* d_out, int out_size)
{
    const float* x  = (const float*)d_in[0];   // [N, D]
    const float* cb = (const float*)d_in[1];   // [K, D]

    float* out = (float*)d_out;
    const size_t predsSz = (size_t)NN * DD;        // 67,108,864
    const size_t simsSz  = (size_t)NN * KK;        // 268,435,456

    // Output layout: [preds | labels | sims]. Labels are int64 in the
    // reference; detect from out_size whether the label region holds raw
    // int64 (2 f32 slots per row) or f32-cast values (1 slot per row).
    size_t labelElems;
    int labels_are_i64;
    if ((size_t)(unsigned)out_size == predsSz + 2 * (size_t)NN + simsSz) {
        labelElems = 2 * (size_t)NN; labels_are_i64 = 1;
    } else {
        labelElems = (size_t)NN;     labels_are_i64 = 0;
    }

    float* preds  = out;
    void*  labels = (void*)(out + predsSz);
    float* sims   = out + predsSz + labelElems;

    dim3 grid(KK / BN, NN / BM);   // (16, 1024)
    sgemm_nt_kernel<<<grid, 256>>>(x, cb, sims);
    argmax_gather_kernel<<<NN, 256>>>(sims, cb, preds, labels, labels_are_i64);
}